// round 15
// baseline (speedup 1.0000x reference)
#include <cuda_runtime.h>
#include <cuda_bf16.h>
#include <cstdint>

// Problem constants (B=2, T=512, C=256, HID=1024)
constexpr int Mrows = 1024;   // B*T
constexpr int Cdim  = 256;
constexpr int Hdim  = 1024;
constexpr int NBLK  = 128;
constexpr int NTHR  = 256;

// Static device scratch
__device__ __nv_bfloat16 g_hid[Mrows * Hdim];
__device__ __nv_bfloat16 g_W2 [Cdim * Hdim];
__device__ int           g_flag[NBLK];   // monotonic per-launch counters

// ---------------------------------------------------------------------------
// PTX helpers
// ---------------------------------------------------------------------------
__device__ __forceinline__ uint32_t smem_u32(const void* p) {
    return (uint32_t)__cvta_generic_to_shared(p);
}
__device__ __forceinline__ void ldsm_x4(uint32_t& r0, uint32_t& r1,
                                        uint32_t& r2, uint32_t& r3, uint32_t a) {
    asm volatile("ldmatrix.sync.aligned.m8n8.x4.shared.b16 {%0,%1,%2,%3},[%4];"
                 : "=r"(r0), "=r"(r1), "=r"(r2), "=r"(r3) : "r"(a));
}
__device__ __forceinline__ void ldsm_x2(uint32_t& r0, uint32_t& r1, uint32_t a) {
    asm volatile("ldmatrix.sync.aligned.m8n8.x2.shared.b16 {%0,%1},[%2];"
                 : "=r"(r0), "=r"(r1) : "r"(a));
}
__device__ __forceinline__ void mma_bf16(float* c, const uint32_t* a, const uint32_t* b) {
    asm volatile(
        "mma.sync.aligned.m16n8k16.row.col.f32.bf16.bf16.f32 "
        "{%0,%1,%2,%3},{%4,%5,%6,%7},{%8,%9},{%0,%1,%2,%3};"
        : "+f"(c[0]), "+f"(c[1]), "+f"(c[2]), "+f"(c[3])
        : "r"(a[0]), "r"(a[1]), "r"(a[2]), "r"(a[3]), "r"(b[0]), "r"(b[1]));
}
__device__ __forceinline__ void cp_async16(uint32_t s, const void* g) {
    asm volatile("cp.async.cg.shared.global [%0], [%1], 16;" :: "r"(s), "l"(g));
}
__device__ __forceinline__ void cp_commit() { asm volatile("cp.async.commit_group;"); }
template <int N> __device__ __forceinline__ void cp_wait() {
    asm volatile("cp.async.wait_group %0;" :: "n"(N));
}
// Convert 8 consecutive fp32 -> 8 bf16 (one 16B store to generic dst)
__device__ __forceinline__ void cvt8(const float* __restrict__ s, void* dst) {
    const float4 v0 = *reinterpret_cast<const float4*>(s);
    const float4 v1 = *reinterpret_cast<const float4*>(s + 4);
    __nv_bfloat162 h[4];
    h[0].x = __float2bfloat16(v0.x); h[0].y = __float2bfloat16(v0.y);
    h[1].x = __float2bfloat16(v0.z); h[1].y = __float2bfloat16(v0.w);
    h[2].x = __float2bfloat16(v1.x); h[2].y = __float2bfloat16(v1.y);
    h[3].x = __float2bfloat16(v1.z); h[3].y = __float2bfloat16(v1.w);
    *reinterpret_cast<uint4*>(dst) = *reinterpret_cast<uint4*>(h);
}

// ===========================================================================
// Single persistent kernel, ZERO grid barriers.
// Block (mt = bid>>3, nt = bid&7):
//   1. self-convert W2 rows [nt*32, nt*32+32) -> g_W2 (self-consumed later)
//   2. convert W1 rows [nt*128, +128) fp32 -> bf16 smem B-tile
//   3. LN rows [mt*64, +64) -> bf16 smem A-tile   (8x redundant, sync-free)
//   4. GEMM1 (64x128, K=256 resident, no mainloop barriers) -> g_hid
//   5. publish flag[bid] (monotonic atomicAdd; replay-safe, no reset)
//   6. GEMM2 (64x32, K=1024 in 8 chunks, own chunk first, flag-gated)
// ===========================================================================
constexpr int LDA1 = 264;   // GEMM1 A row stride (bf16)
constexpr int LDB1 = 264;   // GEMM1 B row stride (bf16), full K resident
constexpr int SMEM = (64 * LDA1 + 128 * LDB1) * 2;   // 101376 B (covers GEMM2's 52224)

__global__ void __launch_bounds__(NTHR, 1)
block_fused(const float* __restrict__ x,
            const float* __restrict__ bp,
            const float* __restrict__ g2,
            const float* __restrict__ b2,
            const float* __restrict__ W1,
            const float* __restrict__ bf1,
            const float* __restrict__ W2,
            const float* __restrict__ bf2,
            float* __restrict__ out)
{
    extern __shared__ char smem[];
    __shared__ int s_target;

    const int bid  = blockIdx.x;
    const int tid  = threadIdx.x;
    const int lane = tid & 31;
    const int warp = tid >> 5;
    const int mt   = bid >> 3;
    const int nt   = bid & 7;
    const int m0   = mt * 64;

    // ---------- 1) W2 self-convert: rows nt*32 + (t>>3), cols (t&7)*128 ----
    {
        const int r  = nt * 32 + (tid >> 3);
        const int cb = (tid & 7) * 128;
        const float* src = W2 + (size_t)r * Hdim + cb;
        __nv_bfloat16* dst = g_W2 + (size_t)r * Hdim + cb;
        #pragma unroll
        for (int j = 0; j < 16; j++)
            cvt8(src + j * 8, dst + j * 8);
    }

    // ---------- 2) W1 convert into smem B-tile --------------------------
    {
        __nv_bfloat16* Bs = reinterpret_cast<__nv_bfloat16*>(smem) + 64 * LDA1;
        const int r  = tid >> 1;                    // 128 rows, 2 threads/row
        const int cb = (tid & 1) * 128;
        const float* src = W1 + (size_t)(nt * 128 + r) * Cdim + cb;
        #pragma unroll
        for (int j = 0; j < 16; j++)
            cvt8(src + j * 8, &Bs[r * LDB1 + cb + j * 8]);
    }

    // ---------- 3) LN into smem A-tile (warp w -> rows w*8..w*8+7) ---------
    {
        __nv_bfloat16* As = reinterpret_cast<__nv_bfloat16*>(smem);
        const int c0 = lane * 8;
        const float4 pa = *reinterpret_cast<const float4*>(bp + c0);
        const float4 pb = *reinterpret_cast<const float4*>(bp + c0 + 4);
        const float4 ga = *reinterpret_cast<const float4*>(g2 + c0);
        const float4 gb = *reinterpret_cast<const float4*>(g2 + c0 + 4);
        const float4 ba = *reinterpret_cast<const float4*>(b2 + c0);
        const float4 bb = *reinterpret_cast<const float4*>(b2 + c0 + 4);
        const float gg[8]  = {ga.x, ga.y, ga.z, ga.w, gb.x, gb.y, gb.z, gb.w};
        const float bbv[8] = {ba.x, ba.y, ba.z, ba.w, bb.x, bb.y, bb.z, bb.w};
        const float pp[8]  = {pa.x, pa.y, pa.z, pa.w, pb.x, pb.y, pb.z, pb.w};
        #pragma unroll
        for (int rr = 0; rr < 8; rr++) {
            const int row = warp * 8 + rr;
            const float* rp = x + (size_t)(m0 + row) * Cdim + c0;
            const float4 a = *reinterpret_cast<const float4*>(rp);
            const float4 b = *reinterpret_cast<const float4*>(rp + 4);
            float v[8] = {a.x + pp[0], a.y + pp[1], a.z + pp[2], a.w + pp[3],
                          b.x + pp[4], b.y + pp[5], b.z + pp[6], b.w + pp[7]};
            float s = 0.f, q = 0.f;
            #pragma unroll
            for (int j = 0; j < 8; j++) { s += v[j]; q += v[j] * v[j]; }
            #pragma unroll
            for (int o = 16; o > 0; o >>= 1) {
                s += __shfl_xor_sync(0xffffffffu, s, o);
                q += __shfl_xor_sync(0xffffffffu, q, o);
            }
            const float mean = s * (1.0f / Cdim);
            const float var  = q * (1.0f / Cdim) - mean * mean;
            const float inv  = rsqrtf(var + 1e-5f);
            __nv_bfloat162 h[4];
            #pragma unroll
            for (int j = 0; j < 4; j++) {
                h[j].x = __float2bfloat16((v[2*j]   - mean) * inv * gg[2*j]   + bbv[2*j]);
                h[j].y = __float2bfloat16((v[2*j+1] - mean) * inv * gg[2*j+1] + bbv[2*j+1]);
            }
            *reinterpret_cast<uint4*>(&As[row * LDA1 + c0]) =
                *reinterpret_cast<uint4*>(h);
        }
    }

    __threadfence();     // g_W2 stores visible (self-consumed via cp.async later)
    __syncthreads();     // smem A + B tiles complete

    // ---------- 4) GEMM1: 64x128, K=256 resident, no mainloop barriers ----
    {
        const __nv_bfloat16* As = reinterpret_cast<const __nv_bfloat16*>(smem);
        const __nv_bfloat16* Bs = As + 64 * LDA1;
        const int n0 = nt * 128;
        const int wm = warp >> 2;      // 2x4 warps: WM=32, WN=32
        const int wn = warp & 3;

        float acc[2][4][4];
        #pragma unroll
        for (int i = 0; i < 2; i++)
            #pragma unroll
            for (int j = 0; j < 4; j++)
                #pragma unroll
                for (int r = 0; r < 4; r++) acc[i][j][r] = 0.f;

        #pragma unroll
        for (int ks = 0; ks < 256; ks += 16) {
            uint32_t afrag[2][4];
            #pragma unroll
            for (int mtl = 0; mtl < 2; mtl++) {
                const int row = wm * 32 + mtl * 16 + (lane & 15);
                const int col = ks + (lane >> 4) * 8;
                ldsm_x4(afrag[mtl][0], afrag[mtl][1], afrag[mtl][2], afrag[mtl][3],
                        smem_u32(&As[row * LDA1 + col]));
            }
            uint32_t bfrag[4][2];
            #pragma unroll
            for (int ntl = 0; ntl < 4; ntl++) {
                const int row = wn * 32 + ntl * 8 + (lane & 7);
                const int col = ks + ((lane >> 3) & 1) * 8;
                ldsm_x2(bfrag[ntl][0], bfrag[ntl][1],
                        smem_u32(&Bs[row * LDB1 + col]));
            }
            #pragma unroll
            for (int mtl = 0; mtl < 2; mtl++)
                #pragma unroll
                for (int ntl = 0; ntl < 4; ntl++)
                    mma_bf16(acc[mtl][ntl], afrag[mtl], bfrag[ntl]);
        }

        // Epilogue: relu(acc + bf1) -> bf16 g_hid
        #pragma unroll
        for (int mtl = 0; mtl < 2; mtl++) {
            #pragma unroll
            for (int ntl = 0; ntl < 4; ntl++) {
                const int m = m0 + wm * 32 + mtl * 16 + (lane >> 2);
                const int n = n0 + wn * 32 + ntl * 8 + (lane & 3) * 2;
                const float b0 = bf1[n], b1 = bf1[n + 1];
                __nv_bfloat162 p;
                p.x = __float2bfloat16(fmaxf(acc[mtl][ntl][0] + b0, 0.f));
                p.y = __float2bfloat16(fmaxf(acc[mtl][ntl][1] + b1, 0.f));
                *reinterpret_cast<__nv_bfloat162*>(&g_hid[(size_t)m * Hdim + n]) = p;
                p.x = __float2bfloat16(fmaxf(acc[mtl][ntl][2] + b0, 0.f));
                p.y = __float2bfloat16(fmaxf(acc[mtl][ntl][3] + b1, 0.f));
                *reinterpret_cast<__nv_bfloat162*>(&g_hid[(size_t)(m + 8) * Hdim + n]) = p;
            }
        }
    }

    // ---------- 5) Publish hid tile (monotonic flag; replay-safe) ----------
    __threadfence();
    __syncthreads();
    if (tid == 0) s_target = atomicAdd(&g_flag[bid], 1) + 1;
    __syncthreads();
    const int target = s_target;

    // ---------- 6) GEMM2: 64x32, K=1024 in 8 chunks (own chunk first) ------
    {
        constexpr int BM = 64, BN = 32, BK = 128, LDS = 136;
        __nv_bfloat16* As = reinterpret_cast<__nv_bfloat16*>(smem);
        __nv_bfloat16* Bs = As + 2 * BM * LDS;
        const int n0 = nt * 32;
        const int wm = warp >> 1;      // 4x2 warps: WM=16, WN=16
        const int wn = warp & 1;

        auto load_chunk = [&](int buf, int c) {
            __nv_bfloat16* Ab = As + buf * BM * LDS;
            __nv_bfloat16* Bb = Bs + buf * BN * LDS;
            #pragma unroll
            for (int i = tid; i < BM * BK / 8; i += NTHR) {
                const int r = i / (BK / 8), cv = i % (BK / 8);
                cp_async16(smem_u32(&Ab[r * LDS + cv * 8]),
                           &g_hid[(size_t)(m0 + r) * Hdim + c * BK + cv * 8]);
            }
            #pragma unroll
            for (int i = tid; i < BN * BK / 8; i += NTHR) {
                const int r = i / (BK / 8), cv = i % (BK / 8);
                cp_async16(smem_u32(&Bb[r * LDS + cv * 8]),
                           &g_W2[(size_t)(n0 + r) * Hdim + c * BK + cv * 8]);
            }
            cp_commit();
        };
        auto wait_chunk = [&](int c) {
            if (tid == 0) {
                while (*(volatile int*)&g_flag[mt * 8 + c] < target) { }
            }
            __syncthreads();
        };

        float acc[2][4] = {};
        load_chunk(0, nt);   // own chunk: produced by self, no wait

        for (int i = 0; i < 8; i++) {
            const int buf = i & 1;
            if (i + 1 < 8) {
                const int cn = (nt + i + 1) & 7;
                wait_chunk(cn);
                load_chunk((i + 1) & 1, cn);
                cp_wait<1>();
            } else {
                cp_wait<0>();
            }
            __syncthreads();

            const __nv_bfloat16* Ab = As + buf * BM * LDS;
            const __nv_bfloat16* Bb = Bs + buf * BN * LDS;
            #pragma unroll
            for (int ks = 0; ks < BK; ks += 16) {
                uint32_t afrag[4];
                {
                    const int row = wm * 16 + (lane & 15);
                    const int col = ks + (lane >> 4) * 8;
                    ldsm_x4(afrag[0], afrag[1], afrag[2], afrag[3],
                            smem_u32(&Ab[row * LDS + col]));
                }
                uint32_t bfrag[2][2];
                #pragma unroll
                for (int ntl = 0; ntl < 2; ntl++) {
                    const int row = wn * 16 + ntl * 8 + (lane & 7);
                    const int col = ks + ((lane >> 3) & 1) * 8;
                    ldsm_x2(bfrag[ntl][0], bfrag[ntl][1],
                            smem_u32(&Bb[row * LDS + col]));
                }
                #pragma unroll
                for (int ntl = 0; ntl < 2; ntl++)
                    mma_bf16(acc[ntl], afrag, bfrag[ntl]);
            }
            __syncthreads();
        }

        // Epilogue: acc + x + bp + bf2 -> fp32 out
        #pragma unroll
        for (int ntl = 0; ntl < 2; ntl++) {
            const int m = m0 + wm * 16 + (lane >> 2);
            const int n = n0 + wn * 16 + ntl * 8 + (lane & 3) * 2;
            const float b0 = bp[n] + bf2[n];
            const float b1 = bp[n + 1] + bf2[n + 1];
            const float2 r0 = *reinterpret_cast<const float2*>(&x[(size_t)m * Cdim + n]);
            const float2 r1 = *reinterpret_cast<const float2*>(&x[(size_t)(m + 8) * Cdim + n]);
            float2 p;
            p.x = acc[ntl][0] + r0.x + b0; p.y = acc[ntl][1] + r0.y + b1;
            *reinterpret_cast<float2*>(&out[(size_t)m * Cdim + n]) = p;
            p.x = acc[ntl][2] + r1.x + b0; p.y = acc[ntl][3] + r1.y + b1;
            *reinterpret_cast<float2*>(&out[(size_t)(m + 8) * Cdim + n]) = p;
        }
    }
}

// ---------------------------------------------------------------------------
// Attention branch is exactly 0 (transform *= 0.0)  =>  sa == bp.
//   y = (x + bp) + relu(LN(x+bp)@W1^T + bf1) @ W2^T + bf2
// Inputs: 0:x 1:Wt 2:Wp 3:bp 4:g1 5:b1 6:g2 7:b2 8:W1 9:bf1 10:W2 11:bf2
// ---------------------------------------------------------------------------
extern "C" void kernel_launch(void* const* d_in, const int* in_sizes, int n_in,
                              void* d_out, int out_size)
{
    const float* x   = (const float*)d_in[0];
    const float* bp  = (const float*)d_in[3];
    const float* g2  = (const float*)d_in[6];
    const float* b2  = (const float*)d_in[7];
    const float* W1  = (const float*)d_in[8];
    const float* bf1 = (const float*)d_in[9];
    const float* W2  = (const float*)d_in[10];
    const float* bf2 = (const float*)d_in[11];
    float* out = (float*)d_out;

    cudaFuncSetAttribute(block_fused,
                         cudaFuncAttributeMaxDynamicSharedMemorySize, SMEM);
    block_fused<<<NBLK, NTHR, SMEM>>>(x, bp, g2, b2, W1, bf1, W2, bf2, out);
}

// round 16
// speedup vs baseline: 1.5524x; 1.5524x over previous
#include <cuda_runtime.h>
#include <cuda_bf16.h>
#include <cstdint>

// Problem constants (B=2, T=512, C=256, HID=1024)
constexpr int Mrows = 1024;   // B*T
constexpr int Cdim  = 256;
constexpr int Hdim  = 1024;
constexpr int NBLK  = 128;    // persistent grid, all co-resident
constexpr int NTHR  = 256;

// Static device scratch
__device__ __nv_bfloat16 g_h2 [Mrows * Cdim];
__device__ __nv_bfloat16 g_hid[Mrows * Hdim];
__device__ __nv_bfloat16 g_W1 [Hdim * Cdim];
__device__ __nv_bfloat16 g_W2 [Cdim * Hdim];
__device__ unsigned      g_bar;        // monotonic ticket barrier
__device__ int           g_flag[NBLK]; // hid-tile ready flags (reset each launch)

// ---------------------------------------------------------------------------
// PTX helpers
// ---------------------------------------------------------------------------
__device__ __forceinline__ uint32_t smem_u32(const void* p) {
    return (uint32_t)__cvta_generic_to_shared(p);
}
__device__ __forceinline__ void ldsm_x4(uint32_t& r0, uint32_t& r1,
                                        uint32_t& r2, uint32_t& r3, uint32_t a) {
    asm volatile("ldmatrix.sync.aligned.m8n8.x4.shared.b16 {%0,%1,%2,%3},[%4];"
                 : "=r"(r0), "=r"(r1), "=r"(r2), "=r"(r3) : "r"(a));
}
__device__ __forceinline__ void ldsm_x2(uint32_t& r0, uint32_t& r1, uint32_t a) {
    asm volatile("ldmatrix.sync.aligned.m8n8.x2.shared.b16 {%0,%1},[%2];"
                 : "=r"(r0), "=r"(r1) : "r"(a));
}
__device__ __forceinline__ void mma_bf16(float* c, const uint32_t* a, const uint32_t* b) {
    asm volatile(
        "mma.sync.aligned.m16n8k16.row.col.f32.bf16.bf16.f32 "
        "{%0,%1,%2,%3},{%4,%5,%6,%7},{%8,%9},{%0,%1,%2,%3};"
        : "+f"(c[0]), "+f"(c[1]), "+f"(c[2]), "+f"(c[3])
        : "r"(a[0]), "r"(a[1]), "r"(a[2]), "r"(a[3]), "r"(b[0]), "r"(b[1]));
}
__device__ __forceinline__ void cp_async16(uint32_t s, const void* g) {
    asm volatile("cp.async.cg.shared.global [%0], [%1], 16;" :: "r"(s), "l"(g));
}
__device__ __forceinline__ void cp_commit() { asm volatile("cp.async.commit_group;"); }
template <int N> __device__ __forceinline__ void cp_wait() {
    asm volatile("cp.async.wait_group %0;" :: "n"(N));
}
// Convert 8 consecutive fp32 -> 8 bf16 (one 16B store)
__device__ __forceinline__ void cvt8(const float* __restrict__ s, void* dst) {
    const float4 v0 = *reinterpret_cast<const float4*>(s);
    const float4 v1 = *reinterpret_cast<const float4*>(s + 4);
    __nv_bfloat162 h[4];
    h[0].x = __float2bfloat16(v0.x); h[0].y = __float2bfloat16(v0.y);
    h[1].x = __float2bfloat16(v0.z); h[1].y = __float2bfloat16(v0.w);
    h[2].x = __float2bfloat16(v1.x); h[2].y = __float2bfloat16(v1.y);
    h[3].x = __float2bfloat16(v1.z); h[3].y = __float2bfloat16(v1.w);
    *reinterpret_cast<uint4*>(dst) = *reinterpret_cast<uint4*>(h);
}

// Grid barrier: monotonic ticket, graph-replay safe.
__device__ __forceinline__ void grid_barrier() {
    __threadfence();
    __syncthreads();
    if (threadIdx.x == 0) {
        const unsigned t = atomicAdd(&g_bar, 1u);
        const unsigned target = t - (t % NBLK) + NBLK;
        while (*(volatile unsigned*)&g_bar < target) { }
        __threadfence();
    }
    __syncthreads();
}

// ===========================================================================
// Persistent kernel (R14 structure; phase B loads all K upfront):
//   Phase A: flag reset + W1/W2 convert + LN      | grid barrier |
//   Phase B: GEMM1 tile (mt, nt): 4 K-stages issued upfront (max MLP),
//            progressive cp_wait, 4 barriers total -> hid, set flag
//   Phase C: GEMM2 tile (mt, nt); chunk c waits flag[mt*8+c] (own chunk free)
// ===========================================================================
__global__ void __launch_bounds__(NTHR, 1)
block_fused(const float* __restrict__ x,
            const float* __restrict__ bp,
            const float* __restrict__ g2,
            const float* __restrict__ b2,
            const float* __restrict__ W1,
            const float* __restrict__ bf1,
            const float* __restrict__ W2,
            const float* __restrict__ bf2,
            float* __restrict__ out)
{
    extern __shared__ char smem[];
    const int bid  = blockIdx.x;
    const int tid  = threadIdx.x;
    const int lane = tid & 31;
    const int warp = tid >> 5;
    const int mt   = bid >> 3;          // m-strip (16)
    const int nt   = bid & 7;           // n-tile  (8)
    const int m0   = mt * 64;

    // ---------------- Phase A: flag reset + convert + LN -------------------
    if (tid == 0) g_flag[bid] = 0;
    {
        const int i8 = bid * 2048 + tid * 8;
        cvt8(W1 + i8, g_W1 + i8);
        cvt8(W2 + i8, g_W2 + i8);
        // LN: 8 warps, one row each -> rows bid*8 .. bid*8+7
        const int row = bid * 8 + warp;
        const int c0  = lane * 8;
        const float* rp = x + (size_t)row * Cdim + c0;
        float v[8];
        {
            const float4 a  = *reinterpret_cast<const float4*>(rp);
            const float4 b  = *reinterpret_cast<const float4*>(rp + 4);
            const float4 pa = *reinterpret_cast<const float4*>(bp + c0);
            const float4 pb = *reinterpret_cast<const float4*>(bp + c0 + 4);
            v[0] = a.x + pa.x; v[1] = a.y + pa.y; v[2] = a.z + pa.z; v[3] = a.w + pa.w;
            v[4] = b.x + pb.x; v[5] = b.y + pb.y; v[6] = b.z + pb.z; v[7] = b.w + pb.w;
        }
        float s = 0.f, q = 0.f;
        #pragma unroll
        for (int j = 0; j < 8; j++) { s += v[j]; q += v[j] * v[j]; }
        #pragma unroll
        for (int o = 16; o > 0; o >>= 1) {
            s += __shfl_xor_sync(0xffffffffu, s, o);
            q += __shfl_xor_sync(0xffffffffu, q, o);
        }
        const float mean = s * (1.0f / Cdim);
        const float var  = q * (1.0f / Cdim) - mean * mean;
        const float inv  = rsqrtf(var + 1e-5f);
        const float4 ga = *reinterpret_cast<const float4*>(g2 + c0);
        const float4 gb = *reinterpret_cast<const float4*>(g2 + c0 + 4);
        const float4 ba = *reinterpret_cast<const float4*>(b2 + c0);
        const float4 bb = *reinterpret_cast<const float4*>(b2 + c0 + 4);
        const float gg[8]  = {ga.x, ga.y, ga.z, ga.w, gb.x, gb.y, gb.z, gb.w};
        const float bbv[8] = {ba.x, ba.y, ba.z, ba.w, bb.x, bb.y, bb.z, bb.w};
        __nv_bfloat162 o2[4];
        #pragma unroll
        for (int j = 0; j < 4; j++) {
            o2[j].x = __float2bfloat16((v[2*j]   - mean) * inv * gg[2*j]   + bbv[2*j]);
            o2[j].y = __float2bfloat16((v[2*j+1] - mean) * inv * gg[2*j+1] + bbv[2*j+1]);
        }
        *reinterpret_cast<uint4*>(&g_h2[(size_t)row * Cdim + c0]) =
            *reinterpret_cast<uint4*>(o2);
    }

    grid_barrier();

    // ---------------- Phase B: GEMM1 (64 x 128, K=256) ---------------------
    // All 4 K-stages (BK=64) issued upfront into 4 distinct buffers.
    {
        constexpr int BM = 64, BN = 128, BK = 64, LDS = 72;
        __nv_bfloat16* As = reinterpret_cast<__nv_bfloat16*>(smem);        // 4*BM*LDS
        __nv_bfloat16* Bs = As + 4 * BM * LDS;                             // 4*BN*LDS
        const int n0 = nt * 128;
        const int wm = warp >> 2;      // 2x4 warps: WM=32, WN=32
        const int wn = warp & 3;

        // Issue all stages (one commit group per stage, max MLP into L2)
        #pragma unroll
        for (int s = 0; s < 4; s++) {
            const int k0 = s * BK;
            __nv_bfloat16* Ab = As + s * BM * LDS;
            __nv_bfloat16* Bb = Bs + s * BN * LDS;
            #pragma unroll
            for (int i = tid; i < BM * BK / 8; i += NTHR) {
                const int r = i / (BK / 8), cv = i % (BK / 8);
                cp_async16(smem_u32(&Ab[r * LDS + cv * 8]),
                           &g_h2[(size_t)(m0 + r) * Cdim + k0 + cv * 8]);
            }
            #pragma unroll
            for (int i = tid; i < BN * BK / 8; i += NTHR) {
                const int r = i / (BK / 8), cv = i % (BK / 8);
                cp_async16(smem_u32(&Bb[r * LDS + cv * 8]),
                           &g_W1[(size_t)(n0 + r) * Cdim + k0 + cv * 8]);
            }
            cp_commit();
        }

        float acc[2][4][4];
        #pragma unroll
        for (int i = 0; i < 2; i++)
            #pragma unroll
            for (int j = 0; j < 4; j++)
                #pragma unroll
                for (int r = 0; r < 4; r++) acc[i][j][r] = 0.f;

        #pragma unroll
        for (int it = 0; it < 4; it++) {
            switch (it) {              // progressive waits: only stage-0 latency exposed
                case 0: cp_wait<3>(); break;
                case 1: cp_wait<2>(); break;
                case 2: cp_wait<1>(); break;
                default: cp_wait<0>(); break;
            }
            __syncthreads();

            const __nv_bfloat16* Ab = As + it * BM * LDS;
            const __nv_bfloat16* Bb = Bs + it * BN * LDS;
            #pragma unroll
            for (int ks = 0; ks < BK; ks += 16) {
                uint32_t afrag[2][4];
                #pragma unroll
                for (int mtl = 0; mtl < 2; mtl++) {
                    const int row = wm * 32 + mtl * 16 + (lane & 15);
                    const int col = ks + (lane >> 4) * 8;
                    ldsm_x4(afrag[mtl][0], afrag[mtl][1], afrag[mtl][2], afrag[mtl][3],
                            smem_u32(&Ab[row * LDS + col]));
                }
                uint32_t bfrag[4][2];
                #pragma unroll
                for (int ntl = 0; ntl < 4; ntl++) {
                    const int row = wn * 32 + ntl * 8 + (lane & 7);
                    const int col = ks + ((lane >> 3) & 1) * 8;
                    ldsm_x2(bfrag[ntl][0], bfrag[ntl][1],
                            smem_u32(&Bb[row * LDS + col]));
                }
                #pragma unroll
                for (int mtl = 0; mtl < 2; mtl++)
                    #pragma unroll
                    for (int ntl = 0; ntl < 4; ntl++)
                        mma_bf16(acc[mtl][ntl], afrag[mtl], bfrag[ntl]);
            }
            // no trailing barrier: buffers are not reused
        }

        // Epilogue: relu(acc + bf1) -> bf16 g_hid
        #pragma unroll
        for (int mtl = 0; mtl < 2; mtl++) {
            #pragma unroll
            for (int ntl = 0; ntl < 4; ntl++) {
                const int m = m0 + wm * 32 + mtl * 16 + (lane >> 2);
                const int n = n0 + wn * 32 + ntl * 8 + (lane & 3) * 2;
                const float b0 = bf1[n], b1 = bf1[n + 1];
                __nv_bfloat162 p;
                p.x = __float2bfloat16(fmaxf(acc[mtl][ntl][0] + b0, 0.f));
                p.y = __float2bfloat16(fmaxf(acc[mtl][ntl][1] + b1, 0.f));
                *reinterpret_cast<__nv_bfloat162*>(&g_hid[(size_t)m * Hdim + n]) = p;
                p.x = __float2bfloat16(fmaxf(acc[mtl][ntl][2] + b0, 0.f));
                p.y = __float2bfloat16(fmaxf(acc[mtl][ntl][3] + b1, 0.f));
                *reinterpret_cast<__nv_bfloat162*>(&g_hid[(size_t)(m + 8) * Hdim + n]) = p;
            }
        }
    }

    // Publish hid tile
    __threadfence();
    __syncthreads();    // also guards phase-C smem overwrite vs phase-B readers
    if (tid == 0) *(volatile int*)&g_flag[bid] = 1;

    // ---------------- Phase C: GEMM2 (64 x 32, K=1024 in 8 chunks) ---------
    {
        constexpr int BM = 64, BN = 32, BK = 128, LDS = 136;
        __nv_bfloat16* As = reinterpret_cast<__nv_bfloat16*>(smem);
        __nv_bfloat16* Bs = As + 2 * BM * LDS;
        const int n0 = nt * 32;
        const int wm = warp >> 1;      // 4x2 warps: WM=16, WN=16
        const int wn = warp & 1;

        auto load_chunk = [&](int buf, int c) {
            __nv_bfloat16* Ab = As + buf * BM * LDS;
            __nv_bfloat16* Bb = Bs + buf * BN * LDS;
            #pragma unroll
            for (int i = tid; i < BM * BK / 8; i += NTHR) {
                const int r = i / (BK / 8), cv = i % (BK / 8);
                cp_async16(smem_u32(&Ab[r * LDS + cv * 8]),
                           &g_hid[(size_t)(m0 + r) * Hdim + c * BK + cv * 8]);
            }
            #pragma unroll
            for (int i = tid; i < BN * BK / 8; i += NTHR) {
                const int r = i / (BK / 8), cv = i % (BK / 8);
                cp_async16(smem_u32(&Bb[r * LDS + cv * 8]),
                           &g_W2[(size_t)(n0 + r) * Hdim + c * BK + cv * 8]);
            }
            cp_commit();
        };
        auto wait_chunk = [&](int c) {
            if (tid == 0) {
                while (*(volatile int*)&g_flag[mt * 8 + c] == 0) { }
            }
            __syncthreads();
        };

        float acc[2][4] = {};
        load_chunk(0, nt);   // own chunk: produced by self, no wait

        for (int i = 0; i < 8; i++) {
            const int buf = i & 1;
            if (i + 1 < 8) {
                const int cn = (nt + i + 1) & 7;
                wait_chunk(cn);
                load_chunk((i + 1) & 1, cn);
                cp_wait<1>();
            } else {
                cp_wait<0>();
            }
            __syncthreads();

            const __nv_bfloat16* Ab = As + buf * BM * LDS;
            const __nv_bfloat16* Bb = Bs + buf * BN * LDS;
            #pragma unroll
            for (int ks = 0; ks < BK; ks += 16) {
                uint32_t afrag[4];
                {
                    const int row = wm * 16 + (lane & 15);
                    const int col = ks + (lane >> 4) * 8;
                    ldsm_x4(afrag[0], afrag[1], afrag[2], afrag[3],
                            smem_u32(&Ab[row * LDS + col]));
                }
                uint32_t bfrag[2][2];
                #pragma unroll
                for (int ntl = 0; ntl < 2; ntl++) {
                    const int row = wn * 16 + ntl * 8 + (lane & 7);
                    const int col = ks + ((lane >> 3) & 1) * 8;
                    ldsm_x2(bfrag[ntl][0], bfrag[ntl][1],
                            smem_u32(&Bb[row * LDS + col]));
                }
                #pragma unroll
                for (int ntl = 0; ntl < 2; ntl++)
                    mma_bf16(acc[ntl], afrag, bfrag[ntl]);
            }
            __syncthreads();
        }

        // Epilogue: acc + x + bp + bf2 -> fp32 out
        #pragma unroll
        for (int ntl = 0; ntl < 2; ntl++) {
            const int m = m0 + wm * 16 + (lane >> 2);
            const int n = n0 + wn * 16 + ntl * 8 + (lane & 3) * 2;
            const float b0 = bp[n] + bf2[n];
            const float b1 = bp[n + 1] + bf2[n + 1];
            const float2 r0 = *reinterpret_cast<const float2*>(&x[(size_t)m * Cdim + n]);
            const float2 r1 = *reinterpret_cast<const float2*>(&x[(size_t)(m + 8) * Cdim + n]);
            float2 p;
            p.x = acc[ntl][0] + r0.x + b0; p.y = acc[ntl][1] + r0.y + b1;
            *reinterpret_cast<float2*>(&out[(size_t)m * Cdim + n]) = p;
            p.x = acc[ntl][2] + r1.x + b0; p.y = acc[ntl][3] + r1.y + b1;
            *reinterpret_cast<float2*>(&out[(size_t)(m + 8) * Cdim + n]) = p;
        }
    }
}

// ---------------------------------------------------------------------------
// Attention branch is exactly 0 (transform *= 0.0)  =>  sa == bp.
//   y = (x + bp) + relu(LN(x+bp)@W1^T + bf1) @ W2^T + bf2
// Inputs: 0:x 1:Wt 2:Wp 3:bp 4:g1 5:b1 6:g2 7:b2 8:W1 9:bf1 10:W2 11:bf2
// ---------------------------------------------------------------------------
extern "C" void kernel_launch(void* const* d_in, const int* in_sizes, int n_in,
                              void* d_out, int out_size)
{
    const float* x   = (const float*)d_in[0];
    const float* bp  = (const float*)d_in[3];
    const float* g2  = (const float*)d_in[6];
    const float* b2  = (const float*)d_in[7];
    const float* W1  = (const float*)d_in[8];
    const float* bf1 = (const float*)d_in[9];
    const float* W2  = (const float*)d_in[10];
    const float* bf2 = (const float*)d_in[11];
    float* out = (float*)d_out;

    // smem = max(phase B, phase C):
    //   B: 4*(64*72 + 128*72)*2 = 110592 ;  C: 2*(64*136 + 32*136)*2 = 52224
    constexpr int SMEM = 4 * (64 * 72 + 128 * 72) * 2;
    cudaFuncSetAttribute(block_fused,
                         cudaFuncAttributeMaxDynamicSharedMemorySize, SMEM);

    block_fused<<<NBLK, NTHR, SMEM>>>(x, bp, g2, b2, W1, bf1, W2, bf2, out);
}